// round 6
// baseline (speedup 1.0000x reference)
#include <cuda_runtime.h>

#define N_  256
#define P_  5
#define H_  32
#define B_  256
#define K_  1280            // N_*P_
#define THRESH_ 0.01f

#define SPLITK 16
#define KC 80               // K per chunk = 16 j exactly
#define JC 16               // j per chunk

// ---- scratch ----
__device__ float g_part[SPLITK][B_ * N_]; // split-K partials [z][b][i]

// ---------------------------------------------------------------
// Fused GEMM: generates act/effw tiles in smem from raw inputs,
// computes C[b][i] partials over its K-chunk, folds bias chunk.
// grid = (4 i-tiles, 4 b-tiles, 16 k-chunks), 256 threads.
// ---------------------------------------------------------------
__global__ __launch_bounds__(256)
void gemm_fused(const float* __restrict__ x,
                const float* __restrict__ adj,
                const float* __restrict__ bp,
                const float* __restrict__ w_pw,
                const float* __restrict__ b_pw)
{
    __shared__ float As[KC][64];      // act:  [k][b]
    __shared__ float Bs[KC][64];      // effw: [k][i]
    __shared__ float adj_s[JC][64];   // masked adjacency.T chunk: [j][i]
    __shared__ float bp_s[KC];
    __shared__ float bsum[4][64];     // bias chunk partials

    const int tid = threadIdx.x;
    const int i0  = blockIdx.x * 64;
    const int b0  = blockIdx.y * 64;
    const int j0  = blockIdx.z * JC;
    const int kc0 = j0 * P_;

    // ---- stage bp chunk + masked adj chunk ----
    if (tid < KC) bp_s[tid] = bp[kc0 + tid];
    {
        const int j  = tid >> 4;          // 0..15
        const int i4 = (tid & 15) * 4;    // 0..60
        float4 e = *reinterpret_cast<const float4*>(adj + (size_t)(j0 + j) * N_ + i0 + i4);
        const int gj = j0 + j;
        adj_s[j][i4 + 0] = (e.x > THRESH_ && (i0 + i4 + 0) != gj) ? e.x : 0.f;
        adj_s[j][i4 + 1] = (e.y > THRESH_ && (i0 + i4 + 1) != gj) ? e.y : 0.f;
        adj_s[j][i4 + 2] = (e.z > THRESH_ && (i0 + i4 + 2) != gj) ? e.z : 0.f;
        adj_s[j][i4 + 3] = (e.w > THRESH_ && (i0 + i4 + 3) != gj) ? e.w : 0.f;
    }
    __syncthreads();

    // ---- generate effw tile: Bs[k][i] = adj_s[j(k)][i] * w_pw[i][k] ----
    {
        const int r = tid >> 2;           // i-local 0..63
        const int q = tid & 3;
        #pragma unroll
        for (int c = 0; c < 5; ++c) {
            const int kq = c * 16 + q * 4;
            float4 w = *reinterpret_cast<const float4*>(
                w_pw + (size_t)(i0 + r) * K_ + kc0 + kq);
            Bs[kq + 0][r] = adj_s[(kq + 0) / P_][r] * w.x;
            Bs[kq + 1][r] = adj_s[(kq + 1) / P_][r] * w.y;
            Bs[kq + 2][r] = adj_s[(kq + 2) / P_][r] * w.z;
            Bs[kq + 3][r] = adj_s[(kq + 3) / P_][r] * w.w;
        }
    }
    // ---- generate act tile: As[k][b] = relu(x[b, j(k)] - bp[k]) ----
    {
        const int r = tid & 63;           // b-local
        const int q = tid >> 6;           // 0..3 -> j sub-range
        float4 xv = *reinterpret_cast<const float4*>(
            x + (size_t)(b0 + r) * N_ + j0 + q * 4);
        float xl[4] = {xv.x, xv.y, xv.z, xv.w};
        #pragma unroll
        for (int jj = 0; jj < 4; ++jj) {
            const float xj = xl[jj];
            const int jl = q * 4 + jj;
            #pragma unroll
            for (int p = 0; p < P_; ++p) {
                const int k = jl * P_ + p;
                As[k][r] = fmaxf(xj - bp_s[k], 0.f);
            }
        }
    }
    // ---- bias chunk partials: bsum[q][i] = sum over 4 j of eff * b_pw ----
    {
        const int il = tid & 63;
        const int q  = tid >> 6;
        float4 bpv = *reinterpret_cast<const float4*>(
            b_pw + (size_t)(i0 + il) * N_ + j0 + q * 4);
        float s = adj_s[q * 4 + 0][il] * bpv.x;
        s = fmaf(adj_s[q * 4 + 1][il], bpv.y, s);
        s = fmaf(adj_s[q * 4 + 2][il], bpv.z, s);
        s = fmaf(adj_s[q * 4 + 3][il], bpv.w, s);
        bsum[q][il] = s;
    }
    __syncthreads();

    // ---- main loop: 4x4 register tile over 80 k ----
    const int tx = tid & 15;   // i direction
    const int ty = tid >> 4;   // b direction
    float acc[4][4] = {};

    #pragma unroll 8
    for (int k = 0; k < KC; ++k) {
        float4 a4 = *reinterpret_cast<const float4*>(&As[k][ty * 4]);
        float4 b4 = *reinterpret_cast<const float4*>(&Bs[k][tx * 4]);
        acc[0][0] = fmaf(a4.x, b4.x, acc[0][0]);
        acc[0][1] = fmaf(a4.x, b4.y, acc[0][1]);
        acc[0][2] = fmaf(a4.x, b4.z, acc[0][2]);
        acc[0][3] = fmaf(a4.x, b4.w, acc[0][3]);
        acc[1][0] = fmaf(a4.y, b4.x, acc[1][0]);
        acc[1][1] = fmaf(a4.y, b4.y, acc[1][1]);
        acc[1][2] = fmaf(a4.y, b4.z, acc[1][2]);
        acc[1][3] = fmaf(a4.y, b4.w, acc[1][3]);
        acc[2][0] = fmaf(a4.z, b4.x, acc[2][0]);
        acc[2][1] = fmaf(a4.z, b4.y, acc[2][1]);
        acc[2][2] = fmaf(a4.z, b4.z, acc[2][2]);
        acc[2][3] = fmaf(a4.z, b4.w, acc[2][3]);
        acc[3][0] = fmaf(a4.w, b4.x, acc[3][0]);
        acc[3][1] = fmaf(a4.w, b4.y, acc[3][1]);
        acc[3][2] = fmaf(a4.w, b4.z, acc[3][2]);
        acc[3][3] = fmaf(a4.w, b4.w, acc[3][3]);
    }

    // ---- add bias chunk (once per (b,i,z) across the grid) and store ----
    #pragma unroll
    for (int v = 0; v < 4; ++v) {
        const int il = tx * 4 + v;
        float bsv = bsum[0][il] + bsum[1][il] + bsum[2][il] + bsum[3][il];
        acc[0][v] += bsv; acc[1][v] += bsv; acc[2][v] += bsv; acc[3][v] += bsv;
    }

    float* dst = g_part[blockIdx.z];
    #pragma unroll
    for (int u = 0; u < 4; ++u) {
        float4 v = make_float4(acc[u][0], acc[u][1], acc[u][2], acc[u][3]);
        *reinterpret_cast<float4*>(&dst[(b0 + ty * 4 + u) * N_ + i0 + tx * 4]) = v;
    }
}

// ---------------------------------------------------------------
// epilogue: reduce split-K partials + per-node MLP.
// Per-thread W rows are single 128B lines -> L1-resident, no transpose needed.
// ---------------------------------------------------------------
__global__ __launch_bounds__(256)
void epi_kernel(const float* __restrict__ W1,
                const float* __restrict__ b1,
                const float* __restrict__ W2,
                const float* __restrict__ b2,
                float* __restrict__ out)
{
    const int b = blockIdx.x;
    const int i = threadIdx.x;

    float c = 0.f;
    #pragma unroll
    for (int s = 0; s < SPLITK; ++s)
        c += g_part[s][b * N_ + i];

    const float* w1r = W1 + i * H_;
    const float* b1r = b1 + i * H_;
    const float* w2r = W2 + i * 2 * H_;

    float m  = b2[i * 2 + 0];
    float sd = b2[i * 2 + 1];
    #pragma unroll
    for (int k = 0; k < H_; ++k) {
        float h = fmaxf(fmaf(c, w1r[k], b1r[k]), 0.f);
        m  = fmaf(w2r[k],      h, m);
        sd = fmaf(w2r[H_ + k], h, sd);
    }
    out[b * N_ + i]                   = m;
    out[(size_t)B_ * N_ + b * N_ + i] = sd;
}

extern "C" void kernel_launch(void* const* d_in, const int* in_sizes, int n_in,
                              void* d_out, int out_size)
{
    const float* x    = (const float*)d_in[0];
    const float* adj  = (const float*)d_in[1];
    const float* bp   = (const float*)d_in[2];
    const float* w_pw = (const float*)d_in[3];
    const float* b_pw = (const float*)d_in[4];
    const float* W1   = (const float*)d_in[5];
    const float* b1   = (const float*)d_in[6];
    const float* W2   = (const float*)d_in[7];
    const float* b2   = (const float*)d_in[8];
    float* out = (float*)d_out;

    gemm_fused<<<dim3(4, 4, SPLITK), 256>>>(x, adj, bp, w_pw, b_pw);
    epi_kernel<<<B_, 256>>>(W1, b1, W2, b2, out);
}

// round 7
// speedup vs baseline: 3.0361x; 3.0361x over previous
#include <cuda_runtime.h>

#define N_  256
#define P_  5
#define H_  32
#define B_  256
#define K_  1280            // N_*P_
#define THRESH_ 0.01f

#define SPLITK 16
#define KC 80               // K per chunk = 16 j exactly
#define JC 16               // j per chunk

// ---- scratch ----
__device__ float g_part[SPLITK][B_ * N_]; // split-K partials [z][b][i]

// ---------------------------------------------------------------
// Fused GEMM: generates act/effw tiles in smem from raw inputs,
// computes C[b][i] partials over its K-chunk, folds bias chunk.
// grid = (4 i-tiles, 4 b-tiles, 16 k-chunks), 256 threads.
// ---------------------------------------------------------------
__global__ __launch_bounds__(256)
void gemm_fused(const float* __restrict__ x,
                const float* __restrict__ adj,
                const float* __restrict__ bp,
                const float* __restrict__ w_pw,
                const float* __restrict__ b_pw)
{
    __shared__ float As[KC][64];      // act:  [k][b]
    __shared__ float Bs[KC][64];      // effw: [k][i]
    __shared__ float adj_s[JC][64];   // masked adjacency.T chunk: [j][i]
    __shared__ float bp_s[KC];
    __shared__ float bsum[4][64];     // bias chunk partials

    const int tid = threadIdx.x;
    const int i0  = blockIdx.x * 64;
    const int b0  = blockIdx.y * 64;
    const int j0  = blockIdx.z * JC;
    const int kc0 = j0 * P_;

    // ---- stage bp chunk + masked adj chunk ----
    if (tid < KC) bp_s[tid] = bp[kc0 + tid];
    {
        const int j  = tid >> 4;          // 0..15
        const int i4 = (tid & 15) * 4;    // 0..60
        float4 e = *reinterpret_cast<const float4*>(adj + (size_t)(j0 + j) * N_ + i0 + i4);
        const int gj = j0 + j;
        adj_s[j][i4 + 0] = (e.x > THRESH_ && (i0 + i4 + 0) != gj) ? e.x : 0.f;
        adj_s[j][i4 + 1] = (e.y > THRESH_ && (i0 + i4 + 1) != gj) ? e.y : 0.f;
        adj_s[j][i4 + 2] = (e.z > THRESH_ && (i0 + i4 + 2) != gj) ? e.z : 0.f;
        adj_s[j][i4 + 3] = (e.w > THRESH_ && (i0 + i4 + 3) != gj) ? e.w : 0.f;
    }
    __syncthreads();

    // ---- generate effw tile: Bs[k][i] = adj_s[j(k)][i] * w_pw[i][k] ----
    {
        const int r = tid >> 2;           // i-local 0..63
        const int q = tid & 3;
        #pragma unroll
        for (int c = 0; c < 5; ++c) {
            const int kq = c * 16 + q * 4;
            float4 w = *reinterpret_cast<const float4*>(
                w_pw + (size_t)(i0 + r) * K_ + kc0 + kq);
            Bs[kq + 0][r] = adj_s[(kq + 0) / P_][r] * w.x;
            Bs[kq + 1][r] = adj_s[(kq + 1) / P_][r] * w.y;
            Bs[kq + 2][r] = adj_s[(kq + 2) / P_][r] * w.z;
            Bs[kq + 3][r] = adj_s[(kq + 3) / P_][r] * w.w;
        }
    }
    // ---- generate act tile: As[k][b] = relu(x[b, j(k)] - bp[k]) ----
    {
        const int r = tid & 63;           // b-local
        const int q = tid >> 6;           // 0..3 -> j sub-range
        float4 xv = *reinterpret_cast<const float4*>(
            x + (size_t)(b0 + r) * N_ + j0 + q * 4);
        float xl[4] = {xv.x, xv.y, xv.z, xv.w};
        #pragma unroll
        for (int jj = 0; jj < 4; ++jj) {
            const float xj = xl[jj];
            const int jl = q * 4 + jj;
            #pragma unroll
            for (int p = 0; p < P_; ++p) {
                const int k = jl * P_ + p;
                As[k][r] = fmaxf(xj - bp_s[k], 0.f);
            }
        }
    }
    // ---- bias chunk partials: bsum[q][i] = sum over 4 j of eff * b_pw ----
    {
        const int il = tid & 63;
        const int q  = tid >> 6;
        float4 bpv = *reinterpret_cast<const float4*>(
            b_pw + (size_t)(i0 + il) * N_ + j0 + q * 4);
        float s = adj_s[q * 4 + 0][il] * bpv.x;
        s = fmaf(adj_s[q * 4 + 1][il], bpv.y, s);
        s = fmaf(adj_s[q * 4 + 2][il], bpv.z, s);
        s = fmaf(adj_s[q * 4 + 3][il], bpv.w, s);
        bsum[q][il] = s;
    }
    __syncthreads();

    // ---- main loop: 4x4 register tile over 80 k ----
    const int tx = tid & 15;   // i direction
    const int ty = tid >> 4;   // b direction
    float acc[4][4] = {};

    #pragma unroll 8
    for (int k = 0; k < KC; ++k) {
        float4 a4 = *reinterpret_cast<const float4*>(&As[k][ty * 4]);
        float4 b4 = *reinterpret_cast<const float4*>(&Bs[k][tx * 4]);
        acc[0][0] = fmaf(a4.x, b4.x, acc[0][0]);
        acc[0][1] = fmaf(a4.x, b4.y, acc[0][1]);
        acc[0][2] = fmaf(a4.x, b4.z, acc[0][2]);
        acc[0][3] = fmaf(a4.x, b4.w, acc[0][3]);
        acc[1][0] = fmaf(a4.y, b4.x, acc[1][0]);
        acc[1][1] = fmaf(a4.y, b4.y, acc[1][1]);
        acc[1][2] = fmaf(a4.y, b4.z, acc[1][2]);
        acc[1][3] = fmaf(a4.y, b4.w, acc[1][3]);
        acc[2][0] = fmaf(a4.z, b4.x, acc[2][0]);
        acc[2][1] = fmaf(a4.z, b4.y, acc[2][1]);
        acc[2][2] = fmaf(a4.z, b4.z, acc[2][2]);
        acc[2][3] = fmaf(a4.z, b4.w, acc[2][3]);
        acc[3][0] = fmaf(a4.w, b4.x, acc[3][0]);
        acc[3][1] = fmaf(a4.w, b4.y, acc[3][1]);
        acc[3][2] = fmaf(a4.w, b4.z, acc[3][2]);
        acc[3][3] = fmaf(a4.w, b4.w, acc[3][3]);
    }

    // ---- add bias chunk (once per (b,i,z) across the grid) and store ----
    #pragma unroll
    for (int v = 0; v < 4; ++v) {
        const int il = tx * 4 + v;
        float bsv = bsum[0][il] + bsum[1][il] + bsum[2][il] + bsum[3][il];
        acc[0][v] += bsv; acc[1][v] += bsv; acc[2][v] += bsv; acc[3][v] += bsv;
    }

    float* dst = g_part[blockIdx.z];
    #pragma unroll
    for (int u = 0; u < 4; ++u) {
        float4 v = make_float4(acc[u][0], acc[u][1], acc[u][2], acc[u][3]);
        *reinterpret_cast<float4*>(&dst[(b0 + ty * 4 + u) * N_ + i0 + tx * 4]) = v;
    }
}

// ---------------------------------------------------------------
// epilogue v2: coalesced. grid = (8 i-tiles, 8 b-tiles), 256 threads.
// Stage this block's 32 i-rows of W into smem (coalesced loads,
// transposed [k][il] stores with padding), then each thread does
// (1 il x 4 b) with stride-1/broadcast smem reads.
// ---------------------------------------------------------------
#define EIT 32   // i per epi block
#define EBT 32   // b per epi block

__global__ __launch_bounds__(256)
void epi_kernel(const float* __restrict__ W1,
                const float* __restrict__ b1,
                const float* __restrict__ W2,
                const float* __restrict__ b2,
                float* __restrict__ out)
{
    __shared__ float w1s[H_][EIT + 1];
    __shared__ float b1s[H_][EIT + 1];
    __shared__ float w2m[H_][EIT + 1];
    __shared__ float w2s[H_][EIT + 1];
    __shared__ float b2s[2][EIT];

    const int tid = threadIdx.x;
    const int i0  = blockIdx.x * EIT;
    const int b0  = blockIdx.y * EBT;

    // ---- stage weights, coalesced global reads ----
    {
        // W1/b1: 32 i x 32 k; consecutive tid -> consecutive k of one row.
        const int il = tid >> 5;          // 0..7
        const int k  = tid & 31;
        #pragma unroll
        for (int r = 0; r < 4; ++r) {
            const int i = il + r * 8;
            w1s[k][i] = W1[(i0 + i) * H_ + k];
            b1s[k][i] = b1[(i0 + i) * H_ + k];
        }
        // W2: 32 i x 64 o; o = tid&63.
        const int il2 = tid >> 6;         // 0..3
        const int o   = tid & 63;
        #pragma unroll
        for (int r = 0; r < 8; ++r) {
            const int i = il2 + r * 4;
            float v = W2[(i0 + i) * 2 * H_ + o];
            if (o < H_) w2m[o][i] = v;
            else        w2s[o - H_][i] = v;
        }
        if (tid < 2 * EIT) {
            const int i = tid >> 1;
            b2s[tid & 1][i] = b2[(i0 + i) * 2 + (tid & 1)];
        }
    }
    __syncthreads();

    const int il = tid & 31;              // lane -> i (coalesced)
    const int bq = tid >> 5;              // warp -> b group
    const int gi = i0 + il;

    // ---- reduce split-K partials: fully coalesced (consecutive lanes = consecutive i)
    float c[4] = {0.f, 0.f, 0.f, 0.f};
    #pragma unroll
    for (int s = 0; s < SPLITK; ++s) {
        const float* src = g_part[s];
        #pragma unroll
        for (int u = 0; u < 4; ++u)
            c[u] += src[(size_t)(b0 + bq * 4 + u) * N_ + gi];
    }

    // ---- MLP: smem reads are stride-1 across lanes (conflict-free) ----
    #pragma unroll
    for (int u = 0; u < 4; ++u) {
        const int b = b0 + bq * 4 + u;
        float m  = b2s[0][il];
        float sd = b2s[1][il];
        #pragma unroll
        for (int k = 0; k < H_; ++k) {
            float h = fmaxf(fmaf(c[u], w1s[k][il], b1s[k][il]), 0.f);
            m  = fmaf(w2m[k][il], h, m);
            sd = fmaf(w2s[k][il], h, sd);
        }
        out[(size_t)b * N_ + gi]            = m;
        out[(size_t)(B_ + b) * N_ + gi]     = sd;
    }
}

extern "C" void kernel_launch(void* const* d_in, const int* in_sizes, int n_in,
                              void* d_out, int out_size)
{
    const float* x    = (const float*)d_in[0];
    const float* adj  = (const float*)d_in[1];
    const float* bp   = (const float*)d_in[2];
    const float* w_pw = (const float*)d_in[3];
    const float* b_pw = (const float*)d_in[4];
    const float* W1   = (const float*)d_in[5];
    const float* b1   = (const float*)d_in[6];
    const float* W2   = (const float*)d_in[7];
    const float* b2   = (const float*)d_in[8];
    float* out = (float*)d_out;

    gemm_fused<<<dim3(4, 4, SPLITK), 256>>>(x, adj, bp, w_pw, b_pw);
    epi_kernel<<<dim3(N_ / EIT, B_ / EBT), 256>>>(W1, b1, W2, b2, out);
}